// round 11
// baseline (speedup 1.0000x reference)
#include <cuda_runtime.h>
#include <cuda_bf16.h>
#include <cstdint>

// ============================================================================
// Problem constants
// ============================================================================
#define B_ROWS 4096
#define D_DIM  1024
#define TEMP   0.2f

// GEMM tiling: sim[4096,4096] = z_j (M side) @ z_i^T (N side), fp8 e4m3 operands
#define TM 256
#define TN 128
#define KC 128                           // fp8 per K-chunk = 128 bytes/row
#define NCHUNK (D_DIM / KC)              // 8
#define CHUNK_MAT_BYTES (B_ROWS * 128)   // 524288 bytes per chunk-slab per matrix

#define A_TILE_BYTES (TM * 128)          // 32768
#define B_TILE_BYTES (TN * 128)          // 16384
#define STAGE_BYTES  (A_TILE_BYTES + B_TILE_BYTES)   // 49152
#define NSTAGE 4

// SMEM: [0..1024) control/reduction, then 4 stages of (A tile | B tile)
#define SMEM_TOTAL (1024 + NSTAGE * STAGE_BYTES)     // 197632

#define N_CTAS ((B_ROWS / TM) * (B_ROWS / TN))       // 16 * 32 = 512

// ============================================================================
// Device scratch (static __device__ globals — no allocation allowed)
// fp8 e4m3, chunk-major, pre-swizzled (SW128): within each 512KB chunk slab,
//   byte offset = SWZ128(row*128 + kbyte). cp.async copies verbatim; smem
//   lands ldmatrix-ready with zero bank conflicts.
// ============================================================================
__device__ __align__(1024) uint8_t g_zj[(size_t)B_ROWS * D_DIM];  // M side (emb_j)
__device__ __align__(1024) uint8_t g_zi[(size_t)B_ROWS * D_DIM];  // N side (emb_i)
__device__ float g_partials[2 * N_CTAS];

// ============================================================================
// PTX helpers — base-target only: cp.async (sm_80), ldmatrix (sm_75),
// fp8 mma.sync m16n8k32 (sm_89+, NOT arch-specific), cvt e4m3x2 (sm_89+)
// ============================================================================
__device__ __forceinline__ uint32_t smem_to_u32(const void* smem_ptr) {
    uint32_t addr;
    asm("{ .reg .u64 tmp; cvta.to.shared.u64 tmp, %1; cvt.u32.u64 %0, tmp; }"
        : "=r"(addr) : "l"(smem_ptr));
    return addr;
}

#define SWZ128(o) ((o) ^ (((o) >> 3) & 0x70))

__device__ __forceinline__ void cp_async16(uint32_t dst, const void* src) {
    asm volatile("cp.async.cg.shared.global [%0], [%1], 16;"
        :: "r"(dst), "l"(src) : "memory");
}
#define CP_COMMIT() asm volatile("cp.async.commit_group;" ::: "memory")
#define CP_WAIT(n)  asm volatile("cp.async.wait_group %0;" :: "n"(n) : "memory")

__device__ __forceinline__ void ldsm_x4(uint32_t* r, uint32_t addr) {
    asm volatile("ldmatrix.sync.aligned.m8n8.x4.shared.b16 {%0,%1,%2,%3}, [%4];"
        : "=r"(r[0]), "=r"(r[1]), "=r"(r[2]), "=r"(r[3]) : "r"(addr));
}

// fp8 e4m3 MMA, k32: byte-level fragment layout identical to bf16 k16 with
// each b16 element = 2 k-consecutive fp8. Same ldmatrix pattern feeds it.
__device__ __forceinline__ void mma16832_e4m3(float* d, const uint32_t* a,
                                              const uint32_t* b) {
    asm volatile(
        "mma.sync.aligned.m16n8k32.row.col.f32.e4m3.e4m3.f32 "
        "{%0,%1,%2,%3}, {%4,%5,%6,%7}, {%8,%9}, {%0,%1,%2,%3};"
        : "+f"(d[0]), "+f"(d[1]), "+f"(d[2]), "+f"(d[3])
        : "r"(a[0]), "r"(a[1]), "r"(a[2]), "r"(a[3]), "r"(b[0]), "r"(b[1]));
}

// Pack two floats into e4m3x2 (low byte = lo element)
__device__ __forceinline__ uint32_t f2_e4m3x2(float hi, float lo) {
    uint16_t r;
    asm("cvt.rn.satfinite.e4m3x2.f32 %0, %1, %2;" : "=h"(r) : "f"(hi), "f"(lo));
    return (uint32_t)r;
}

// ============================================================================
// Kernel 1: row L2-normalize fp32 -> fp8 e4m3 scratch (chunk-major, swizzled)
// 4096 blocks x 256 threads; block b -> matrix (b>>11), rows 2*(b&2047)+{0,1}
// Each 128-thread half handles one row: 8 elements (2 float4) per thread,
// one uint2 (8 fp8) swizzled store per thread (8B-aligned: swizzle only
// flips bits 4-6, so 8B alignment is preserved).
// ============================================================================
__global__ void __launch_bounds__(256) norm_fp8_kernel(
    const float* __restrict__ emb_i, const float* __restrict__ emb_j) {
    int t = threadIdx.x;
    int half = t >> 7;                       // row within block
    int q = t & 127;                         // element-octet index within row
    int mat = blockIdx.x >> 11;
    int row = ((blockIdx.x & 2047) << 1) + half;

    const float4* src = reinterpret_cast<const float4*>(mat ? emb_j : emb_i)
                        + (size_t)row * (D_DIM / 4);
    char* dstBase = reinterpret_cast<char*>(mat ? g_zj : g_zi);

    float4 v0 = src[2 * q];
    float4 v1 = src[2 * q + 1];
    float ss = v0.x * v0.x + v0.y * v0.y + v0.z * v0.z + v0.w * v0.w
             + v1.x * v1.x + v1.y * v1.y + v1.z * v1.z + v1.w * v1.w;
#pragma unroll
    for (int o = 16; o > 0; o >>= 1) ss += __shfl_xor_sync(0xFFFFFFFFu, ss, o);
    __shared__ float ws[8];
    if ((t & 31) == 0) ws[t >> 5] = ss;
    __syncthreads();
    float tot = ws[half * 4] + ws[half * 4 + 1] + ws[half * 4 + 2] + ws[half * 4 + 3];
    float inv = 1.0f / fmaxf(sqrtf(tot), 1e-12f);

    uint2 pack;
    pack.x = f2_e4m3x2(v0.y * inv, v0.x * inv)
           | (f2_e4m3x2(v0.w * inv, v0.z * inv) << 16);
    pack.y = f2_e4m3x2(v1.y * inv, v1.x * inv)
           | (f2_e4m3x2(v1.w * inv, v1.z * inv) << 16);

    int chunk = q >> 4;                                  // 128-elem K-chunk
    uint32_t off = (uint32_t)row * 128u + (uint32_t)(q & 15) * 8u;
    off = SWZ128(off);                                   // pre-swizzle in GMEM
    *reinterpret_cast<uint2*>(dstBase + (size_t)chunk * CHUNK_MAT_BYTES + off) = pack;
}

// ============================================================================
// Kernel 2: fused fp8 mma.sync GEMM + softplus + reduce
// grid (32, 16): blockIdx.x = tn (TN=128), blockIdx.y = tm (TM=256)
// 512 threads = 16 warps (8 in M x 2 in N), warp tile 32x64.
// 4-stage cp.async pipeline, one __syncthreads per chunk; unconditional
// commit_group keeps wait_group counts exact through the tail.
// ============================================================================
__device__ __forceinline__ void issue_loads(uint32_t dA, uint32_t dB,
                                            const char* srcA, const char* srcB,
                                            int tid) {
    // A tile 32768B = 2048 x 16B slices -> 4 per thread
#pragma unroll
    for (int i = 0; i < 4; i++) {
        uint32_t idx = (uint32_t)tid + 512u * i;
        cp_async16(dA + idx * 16u, srcA + (size_t)idx * 16u);
    }
    // B tile 16384B = 1024 x 16B slices -> 2 per thread
#pragma unroll
    for (int i = 0; i < 2; i++) {
        uint32_t idx = (uint32_t)tid + 512u * i;
        cp_async16(dB + idx * 16u, srcB + (size_t)idx * 16u);
    }
}

__global__ void __launch_bounds__(512, 1) gemm_loss_kernel() {
    extern __shared__ __align__(1024) char smem[];
    uint32_t sb = smem_to_u32(smem);
    int tid = threadIdx.x;
    int wid = tid >> 5, lane = tid & 31;
    int wm = wid >> 1, wn = wid & 1;        // 8 x 2 warp grid
    int tn = blockIdx.x, tm = blockIdx.y;

    uint32_t stA[NSTAGE], stB[NSTAGE];
#pragma unroll
    for (int s = 0; s < NSTAGE; s++) {
        stA[s] = sb + 1024 + s * STAGE_BYTES;
        stB[s] = stA[s] + A_TILE_BYTES;
    }

    const char* gA = reinterpret_cast<const char*>(g_zj) + (size_t)tm * TM * 128;
    const char* gB = reinterpret_cast<const char*>(g_zi) + (size_t)tn * TN * 128;

    // Prologue: chunks 0..NSTAGE-2 into stages 0..NSTAGE-2 (one group each)
#pragma unroll
    for (int c = 0; c < NSTAGE - 1; c++) {
        issue_loads(stA[c], stB[c], gA + (size_t)c * CHUNK_MAT_BYTES,
                    gB + (size_t)c * CHUNK_MAT_BYTES, tid);
        CP_COMMIT();
    }

    // Unswizzled ldmatrix byte offsets; swizzle applied per access so the
    // +kk*32 byte advance (now = k32 in fp8) happens BEFORE the XOR.
    uint32_t aRow[2];
    {
        int r = lane & 15, hb = (lane >> 4) * 16;
#pragma unroll
        for (int i = 0; i < 2; i++)
            aRow[i] = (uint32_t)(wm * 32 + i * 16 + r) * 128u + hb;
    }
    uint32_t bRow[4];
    {
        int rn = (lane & 7) + ((lane >> 4) << 3);
        int bb = ((lane >> 3) & 1) * 16;
#pragma unroll
        for (int j2 = 0; j2 < 4; j2++)
            bRow[j2] = (uint32_t)(wn * 64 + j2 * 16 + rn) * 128u + bb;
    }

    float acc[64];
#pragma unroll
    for (int i = 0; i < 64; i++) acc[i] = 0.0f;

    for (int c = 0; c < NCHUNK; c++) {
        CP_WAIT(NSTAGE - 2);   // chunk c's group retired (groups are exact)
        __syncthreads();       // chunk c visible to all; stage (c-1)%4 free

        int cn = c + NSTAGE - 1;
        if (cn < NCHUNK)
            issue_loads(stA[cn & (NSTAGE - 1)], stB[cn & (NSTAGE - 1)],
                        gA + (size_t)cn * CHUNK_MAT_BYTES,
                        gB + (size_t)cn * CHUNK_MAT_BYTES, tid);
        CP_COMMIT();           // unconditional: tail groups may be empty

        uint32_t baseA = stA[c & (NSTAGE - 1)], baseB = stB[c & (NSTAGE - 1)];
#pragma unroll
        for (int kk = 0; kk < 4; kk++) {   // 4 x k32 = 128 fp8 per chunk
            uint32_t af[2][4], bf[4][4];
            ldsm_x4(af[0], baseA + SWZ128(aRow[0] + kk * 32u));
            ldsm_x4(af[1], baseA + SWZ128(aRow[1] + kk * 32u));
#pragma unroll
            for (int j2 = 0; j2 < 4; j2++)
                ldsm_x4(bf[j2], baseB + SWZ128(bRow[j2] + kk * 32u));
#pragma unroll
            for (int i = 0; i < 2; i++)
#pragma unroll
                for (int j = 0; j < 8; j++)
                    mma16832_e4m3(&acc[(i * 8 + j) * 4], af[i],
                                  &bf[j >> 1][(j & 1) * 2]);
        }
    }

    // ---- fused epilogue: softplus + diagonal split, all in registers ----
    int g = lane >> 2, tig = lane & 3;
    int rowBase = tm * TM + wm * 32;
    int colBase = tn * TN + wn * 64;
    float negs = 0.0f, poss = 0.0f;
#pragma unroll
    for (int i = 0; i < 2; i++) {
#pragma unroll
        for (int j = 0; j < 8; j++) {
            const float* d = &acc[(i * 8 + j) * 4];
#pragma unroll
            for (int r = 0; r < 4; r++) {
                int row = rowBase + i * 16 + g + (r >> 1) * 8;
                int col = colBase + j * 8 + tig * 2 + (r & 1);
                float v = d[r];
                if (row == col) poss += __logf(1.0f + __expf(TEMP - v));
                else            negs += __logf(1.0f + __expf(v - TEMP));
            }
        }
    }
#pragma unroll
    for (int o = 16; o > 0; o >>= 1) {
        negs += __shfl_xor_sync(0xFFFFFFFFu, negs, o);
        poss += __shfl_xor_sync(0xFFFFFFFFu, poss, o);
    }
    float* red = reinterpret_cast<float*>(smem + 32);
    if (lane == 0) { red[wid] = negs; red[16 + wid] = poss; }
    __syncthreads();
    if (tid == 0) {
        float n = 0.0f, p = 0.0f;
#pragma unroll
        for (int w = 0; w < 16; w++) { n += red[w]; p += red[16 + w]; }
        int cta = tm * 32 + tn;
        g_partials[cta * 2]     = n;
        g_partials[cta * 2 + 1] = p;
    }
}

// ============================================================================
// Kernel 3: deterministic final reduction of 512 CTA partials -> scalar loss
// ============================================================================
__global__ void __launch_bounds__(512) finalize_kernel(float* __restrict__ out) {
    __shared__ double s[512];
    int t = threadIdx.x;
    double n = (double)g_partials[t * 2];
    double p = (double)g_partials[t * 2 + 1];
    s[t] = n;
    __syncthreads();
    for (int o = 256; o > 0; o >>= 1) {
        if (t < o) s[t] += s[t + o];
        __syncthreads();
    }
    double ntot = s[0];
    __syncthreads();
    s[t] = p;
    __syncthreads();
    for (int o = 256; o > 0; o >>= 1) {
        if (t < o) s[t] += s[t + o];
        __syncthreads();
    }
    double ptot = s[0];
    if (t == 0) {
        const double Bd = (double)B_ROWS;
        double loss = 0.5 * (ptot / Bd) + 0.5 * (ntot / (Bd * (Bd - 1.0)));
        out[0] = (float)loss;
    }
}

// ============================================================================
// Launcher
// ============================================================================
extern "C" void kernel_launch(void* const* d_in, const int* in_sizes, int n_in,
                              void* d_out, int out_size) {
    (void)in_sizes; (void)n_in; (void)out_size;
    const float* emb_i = (const float*)d_in[0];
    const float* emb_j = (const float*)d_in[1];
    float* out = (float*)d_out;

    cudaFuncSetAttribute(gemm_loss_kernel,
                         cudaFuncAttributeMaxDynamicSharedMemorySize, SMEM_TOTAL);

    norm_fp8_kernel<<<4096, 256>>>(emb_i, emb_j);
    dim3 grid(B_ROWS / TN, B_ROWS / TM);   // (32, 16)
    gemm_loss_kernel<<<grid, 512, SMEM_TOTAL>>>();
    finalize_kernel<<<1, 512>>>(out);
}

// round 12
// speedup vs baseline: 1.1666x; 1.1666x over previous
#include <cuda_runtime.h>
#include <cuda_bf16.h>
#include <cstdint>

// ============================================================================
// Problem constants
// ============================================================================
#define B_ROWS 4096
#define D_DIM  1024
#define TEMP   0.2f

// GEMM tiling: sim[4096,4096] = z_j (M side) @ z_i^T (N side), bf16 operands
#define TM 128
#define TN 128
#define KC 64                            // bf16 per K-chunk = 128 bytes/row
#define NCHUNK (D_DIM / KC)              // 16
#define CHUNK_MAT_BYTES (B_ROWS * 128)   // 524288 bytes per chunk-slab per matrix

#define A_TILE_BYTES (TM * 128)          // 16384
#define B_TILE_BYTES (TN * 128)          // 16384
#define STAGE_BYTES  (A_TILE_BYTES + B_TILE_BYTES)   // 32768
#define NSTAGE 3

// SMEM: [0..1024) control/reduction, then 3 stages of (A tile | B tile)
#define SMEM_TOTAL (1024 + NSTAGE * STAGE_BYTES)     // 99328  -> 2 CTAs/SM

#define N_CTAS ((B_ROWS / TM) * (B_ROWS / TN))       // 32 * 32 = 1024

// ============================================================================
// Device scratch (static __device__ globals — no allocation allowed)
// bf16, chunk-major, pre-swizzled (SW128): within each 512KB chunk slab,
//   byte offset = SWZ128(row*128 + kbyte). cp.async copies verbatim; smem
//   lands ldmatrix-ready with zero bank conflicts.
// ============================================================================
__device__ __align__(1024) __nv_bfloat16 g_zj[(size_t)B_ROWS * D_DIM];  // M side
__device__ __align__(1024) __nv_bfloat16 g_zi[(size_t)B_ROWS * D_DIM];  // N side
__device__ float g_partials[2 * N_CTAS];

// ============================================================================
// PTX helpers — base-target only (sm_80-class): cp.async, ldmatrix, mma.sync
// ============================================================================
__device__ __forceinline__ uint32_t smem_to_u32(const void* smem_ptr) {
    uint32_t addr;
    asm("{ .reg .u64 tmp; cvta.to.shared.u64 tmp, %1; cvt.u32.u64 %0, tmp; }"
        : "=r"(addr) : "l"(smem_ptr));
    return addr;
}

#define SWZ128(o) ((o) ^ (((o) >> 3) & 0x70))

__device__ __forceinline__ void cp_async16(uint32_t dst, const void* src) {
    asm volatile("cp.async.cg.shared.global [%0], [%1], 16;"
        :: "r"(dst), "l"(src) : "memory");
}
#define CP_COMMIT() asm volatile("cp.async.commit_group;" ::: "memory")
#define CP_WAIT(n)  asm volatile("cp.async.wait_group %0;" :: "n"(n) : "memory")

__device__ __forceinline__ void ldsm_x4(uint32_t* r, uint32_t addr) {
    asm volatile("ldmatrix.sync.aligned.m8n8.x4.shared.b16 {%0,%1,%2,%3}, [%4];"
        : "=r"(r[0]), "=r"(r[1]), "=r"(r[2]), "=r"(r[3]) : "r"(addr));
}

__device__ __forceinline__ void mma16816(float* d, const uint32_t* a, const uint32_t* b) {
    asm volatile(
        "mma.sync.aligned.m16n8k16.row.col.f32.bf16.bf16.f32 "
        "{%0,%1,%2,%3}, {%4,%5,%6,%7}, {%8,%9}, {%0,%1,%2,%3};"
        : "+f"(d[0]), "+f"(d[1]), "+f"(d[2]), "+f"(d[3])
        : "r"(a[0]), "r"(a[1]), "r"(a[2]), "r"(a[3]), "r"(b[0]), "r"(b[1]));
}

// ============================================================================
// Kernel 1: row L2-normalize fp32 -> bf16 scratch (chunk-major, pre-swizzled)
// Warp-per-row, NO block barrier, NO smem. 1024 blocks x 256 threads = 8192
// warps = 8192 rows (2 matrices x 4096). Each lane: 32 elems (8 float4),
// pure shfl reduction, 4 uint4 swizzled stores.
// ============================================================================
__global__ void __launch_bounds__(256) norm_bf16_kernel(
    const float* __restrict__ emb_i, const float* __restrict__ emb_j) {
    int wid = threadIdx.x >> 5, lane = threadIdx.x & 31;
    int mat = blockIdx.x >> 9;                       // 0: emb_i, 1: emb_j
    int row = ((blockIdx.x & 511) << 3) + wid;

    const float4* src = reinterpret_cast<const float4*>(mat ? emb_j : emb_i)
                        + (size_t)row * (D_DIM / 4) + lane * 8;
    char* dstBase = reinterpret_cast<char*>(mat ? g_zj : g_zi);

    float4 v[8];
#pragma unroll
    for (int i = 0; i < 8; i++) v[i] = src[i];
    float ss = 0.0f;
#pragma unroll
    for (int i = 0; i < 8; i++)
        ss += v[i].x * v[i].x + v[i].y * v[i].y + v[i].z * v[i].z + v[i].w * v[i].w;
#pragma unroll
    for (int o = 16; o > 0; o >>= 1) ss += __shfl_xor_sync(0xFFFFFFFFu, ss, o);
    float inv = 1.0f / fmaxf(sqrtf(ss), 1e-12f);

    // 4 stores of 8 bf16 each; store o covers elements 32*lane + 8o .. +7
#pragma unroll
    for (int o = 0; o < 4; o++) {
        __nv_bfloat162 p0 = __floats2bfloat162_rn(v[2*o].x * inv, v[2*o].y * inv);
        __nv_bfloat162 p1 = __floats2bfloat162_rn(v[2*o].z * inv, v[2*o].w * inv);
        __nv_bfloat162 p2 = __floats2bfloat162_rn(v[2*o+1].x * inv, v[2*o+1].y * inv);
        __nv_bfloat162 p3 = __floats2bfloat162_rn(v[2*o+1].z * inv, v[2*o+1].w * inv);
        uint4 pack;
        pack.x = *reinterpret_cast<uint32_t*>(&p0);
        pack.y = *reinterpret_cast<uint32_t*>(&p1);
        pack.z = *reinterpret_cast<uint32_t*>(&p2);
        pack.w = *reinterpret_cast<uint32_t*>(&p3);
        int e = 32 * lane + 8 * o;                   // first element of this store
        int chunk = e >> 6;                          // 64-elem K-chunk
        uint32_t off = (uint32_t)row * 128u + (uint32_t)(e & 63) * 2u;
        off = SWZ128(off);
        *reinterpret_cast<uint4*>(dstBase + (size_t)chunk * CHUNK_MAT_BYTES + off) = pack;
    }
}

// ============================================================================
// Kernel 2: fused bf16 mma.sync GEMM + softplus + reduce
// grid (32, 32): blockIdx.x = tn (TN=128), blockIdx.y = tm (TM=128)
// 256 threads = 8 warps (4 in M x 2 in N), warp tile 32x64.
// 3-stage cp.async pipeline, one __syncthreads per chunk; unconditional
// commit_group keeps wait_group counts exact through the tail.
// 2 CTAs/SM: co-resident CTA's mainloop hides this CTA's prologue/epilogue.
// ============================================================================
__device__ __forceinline__ void issue_loads(uint32_t dA, uint32_t dB,
                                            const char* srcA, const char* srcB,
                                            int tid) {
    // A tile 16384B = 1024 x 16B slices -> 4 per thread
#pragma unroll
    for (int i = 0; i < 4; i++) {
        uint32_t idx = (uint32_t)tid + 256u * i;
        cp_async16(dA + idx * 16u, srcA + (size_t)idx * 16u);
    }
    // B tile 16384B = 1024 x 16B slices -> 4 per thread
#pragma unroll
    for (int i = 0; i < 4; i++) {
        uint32_t idx = (uint32_t)tid + 256u * i;
        cp_async16(dB + idx * 16u, srcB + (size_t)idx * 16u);
    }
}

__global__ void __launch_bounds__(256, 2) gemm_loss_kernel() {
    extern __shared__ __align__(1024) char smem[];
    uint32_t sb = smem_to_u32(smem);
    int tid = threadIdx.x;
    int wid = tid >> 5, lane = tid & 31;
    int wm = wid >> 1, wn = wid & 1;        // 4 x 2 warp grid
    int tn = blockIdx.x, tm = blockIdx.y;

    uint32_t stA[NSTAGE], stB[NSTAGE];
#pragma unroll
    for (int s = 0; s < NSTAGE; s++) {
        stA[s] = sb + 1024 + s * STAGE_BYTES;
        stB[s] = stA[s] + A_TILE_BYTES;
    }

    const char* gA = reinterpret_cast<const char*>(g_zj) + (size_t)tm * TM * 128;
    const char* gB = reinterpret_cast<const char*>(g_zi) + (size_t)tn * TN * 128;

    // Prologue: chunks 0..NSTAGE-2 into stages 0..NSTAGE-2 (one group each)
#pragma unroll
    for (int c = 0; c < NSTAGE - 1; c++) {
        issue_loads(stA[c], stB[c], gA + (size_t)c * CHUNK_MAT_BYTES,
                    gB + (size_t)c * CHUNK_MAT_BYTES, tid);
        CP_COMMIT();
    }

    // Unswizzled ldmatrix byte offsets; swizzle applied per access so the
    // +kk*32 column advance happens BEFORE the XOR — no carry corruption.
    uint32_t aRow[2];
    {
        int r = lane & 15, hb = (lane >> 4) * 16;
#pragma unroll
        for (int i = 0; i < 2; i++)
            aRow[i] = (uint32_t)(wm * 32 + i * 16 + r) * 128u + hb;
    }
    uint32_t bRow[4];
    {
        int rn = (lane & 7) + ((lane >> 4) << 3);
        int bb = ((lane >> 3) & 1) * 16;
#pragma unroll
        for (int j2 = 0; j2 < 4; j2++)
            bRow[j2] = (uint32_t)(wn * 64 + j2 * 16 + rn) * 128u + bb;
    }

    float acc[64];
#pragma unroll
    for (int i = 0; i < 64; i++) acc[i] = 0.0f;

    int sIdx = 0;   // stage of chunk c (cycles 0,1,2,0,...)
    for (int c = 0; c < NCHUNK; c++) {
        CP_WAIT(NSTAGE - 2);   // chunk c's group retired (groups are exact)
        __syncthreads();       // chunk c visible; stage of chunk c-1 free

        int cn = c + NSTAGE - 1;
        int sNext = sIdx + (NSTAGE - 1);
        if (sNext >= NSTAGE) sNext -= NSTAGE;
        if (cn < NCHUNK)
            issue_loads(stA[sNext], stB[sNext],
                        gA + (size_t)cn * CHUNK_MAT_BYTES,
                        gB + (size_t)cn * CHUNK_MAT_BYTES, tid);
        CP_COMMIT();           // unconditional: tail groups may be empty

        uint32_t baseA = stA[sIdx], baseB = stB[sIdx];
#pragma unroll
        for (int kk = 0; kk < 4; kk++) {
            uint32_t af[2][4], bf[4][4];
            ldsm_x4(af[0], baseA + SWZ128(aRow[0] + kk * 32u));
            ldsm_x4(af[1], baseA + SWZ128(aRow[1] + kk * 32u));
#pragma unroll
            for (int j2 = 0; j2 < 4; j2++)
                ldsm_x4(bf[j2], baseB + SWZ128(bRow[j2] + kk * 32u));
#pragma unroll
            for (int i = 0; i < 2; i++)
#pragma unroll
                for (int j = 0; j < 8; j++)
                    mma16816(&acc[(i * 8 + j) * 4], af[i], &bf[j >> 1][(j & 1) * 2]);
        }
        sIdx = (sIdx == NSTAGE - 1) ? 0 : sIdx + 1;
    }

    // ---- fused epilogue: softplus + diagonal split, all in registers ----
    int g = lane >> 2, tig = lane & 3;
    int rowBase = tm * TM + wm * 32;
    int colBase = tn * TN + wn * 64;
    float negs = 0.0f, poss = 0.0f;
#pragma unroll
    for (int i = 0; i < 2; i++) {
#pragma unroll
        for (int j = 0; j < 8; j++) {
            const float* d = &acc[(i * 8 + j) * 4];
#pragma unroll
            for (int r = 0; r < 4; r++) {
                int row = rowBase + i * 16 + g + (r >> 1) * 8;
                int col = colBase + j * 8 + tig * 2 + (r & 1);
                float v = d[r];
                if (row == col) poss += __logf(1.0f + __expf(TEMP - v));
                else            negs += __logf(1.0f + __expf(v - TEMP));
            }
        }
    }
#pragma unroll
    for (int o = 16; o > 0; o >>= 1) {
        negs += __shfl_xor_sync(0xFFFFFFFFu, negs, o);
        poss += __shfl_xor_sync(0xFFFFFFFFu, poss, o);
    }
    float* red = reinterpret_cast<float*>(smem + 32);
    if (lane == 0) { red[wid] = negs; red[8 + wid] = poss; }
    __syncthreads();
    if (tid == 0) {
        float n = 0.0f, p = 0.0f;
#pragma unroll
        for (int w = 0; w < 8; w++) { n += red[w]; p += red[8 + w]; }
        int cta = tm * 32 + tn;
        g_partials[cta * 2]     = n;
        g_partials[cta * 2 + 1] = p;
    }
}

// ============================================================================
// Kernel 3: deterministic final reduction of 1024 CTA partials -> scalar loss
// ============================================================================
__global__ void __launch_bounds__(1024) finalize_kernel(float* __restrict__ out) {
    __shared__ double s[1024];
    int t = threadIdx.x;
    double n = (double)g_partials[t * 2];
    double p = (double)g_partials[t * 2 + 1];
    s[t] = n;
    __syncthreads();
    for (int o = 512; o > 0; o >>= 1) {
        if (t < o) s[t] += s[t + o];
        __syncthreads();
    }
    double ntot = s[0];
    __syncthreads();
    s[t] = p;
    __syncthreads();
    for (int o = 512; o > 0; o >>= 1) {
        if (t < o) s[t] += s[t + o];
        __syncthreads();
    }
    double ptot = s[0];
    if (t == 0) {
        const double Bd = (double)B_ROWS;
        double loss = 0.5 * (ptot / Bd) + 0.5 * (ntot / (Bd * (Bd - 1.0)));
        out[0] = (float)loss;
    }
}

// ============================================================================
// Launcher
// ============================================================================
extern "C" void kernel_launch(void* const* d_in, const int* in_sizes, int n_in,
                              void* d_out, int out_size) {
    (void)in_sizes; (void)n_in; (void)out_size;
    const float* emb_i = (const float*)d_in[0];
    const float* emb_j = (const float*)d_in[1];
    float* out = (float*)d_out;

    cudaFuncSetAttribute(gemm_loss_kernel,
                         cudaFuncAttributeMaxDynamicSharedMemorySize, SMEM_TOTAL);

    norm_bf16_kernel<<<1024, 256>>>(emb_i, emb_j);
    dim3 grid(B_ROWS / TN, B_ROWS / TM);   // (32, 32)
    gemm_loss_kernel<<<grid, 256, SMEM_TOTAL>>>();
    finalize_kernel<<<1, 1024>>>(out);
}

// round 13
// speedup vs baseline: 1.2571x; 1.0776x over previous
#include <cuda_runtime.h>
#include <cuda_bf16.h>
#include <cstdint>

// ============================================================================
// Problem constants
// ============================================================================
#define B_ROWS 4096
#define D_DIM  1024
#define TEMP   0.2f

// GEMM tiling: sim[4096,4096] = z_j (M side) @ z_i^T (N side), bf16 operands
#define TM 128
#define TN 128
#define KC 64                            // bf16 per K-chunk = 128 bytes/row
#define NCHUNK (D_DIM / KC)              // 16
#define CHUNK_MAT_BYTES (B_ROWS * 128)   // 524288 bytes per chunk-slab per matrix

#define A_TILE_BYTES (TM * 128)          // 16384
#define B_TILE_BYTES (TN * 128)          // 16384
#define STAGE_BYTES  (A_TILE_BYTES + B_TILE_BYTES)   // 32768
#define NSTAGE 3

// SMEM: [0..1024) control/reduction, then 3 stages of (A tile | B tile)
#define SMEM_TOTAL (1024 + NSTAGE * STAGE_BYTES)     // 99328  -> 2 CTAs/SM

#define N_CTAS ((B_ROWS / TM) * (B_ROWS / TN))       // 32 * 32 = 1024

// ============================================================================
// Device scratch (static __device__ globals — no allocation allowed)
// bf16, chunk-major, pre-swizzled (SW128): within each 512KB chunk slab,
//   byte offset = SWZ128(row*128 + kbyte). cp.async copies verbatim; smem
//   lands ldmatrix-ready with zero bank conflicts.
// ============================================================================
__device__ __align__(1024) __nv_bfloat16 g_zj[(size_t)B_ROWS * D_DIM];  // M side
__device__ __align__(1024) __nv_bfloat16 g_zi[(size_t)B_ROWS * D_DIM];  // N side
__device__ float g_partials[2 * N_CTAS];

// ============================================================================
// PTX helpers — base-target only (sm_80-class): cp.async, ldmatrix, mma.sync
// ============================================================================
__device__ __forceinline__ uint32_t smem_to_u32(const void* smem_ptr) {
    uint32_t addr;
    asm("{ .reg .u64 tmp; cvta.to.shared.u64 tmp, %1; cvt.u32.u64 %0, tmp; }"
        : "=r"(addr) : "l"(smem_ptr));
    return addr;
}

#define SWZ128(o) ((o) ^ (((o) >> 3) & 0x70))

__device__ __forceinline__ void cp_async16(uint32_t dst, const void* src) {
    asm volatile("cp.async.cg.shared.global [%0], [%1], 16;"
        :: "r"(dst), "l"(src) : "memory");
}
#define CP_COMMIT() asm volatile("cp.async.commit_group;" ::: "memory")
#define CP_WAIT(n)  asm volatile("cp.async.wait_group %0;" :: "n"(n) : "memory")

__device__ __forceinline__ void ldsm_x4(uint32_t* r, uint32_t addr) {
    asm volatile("ldmatrix.sync.aligned.m8n8.x4.shared.b16 {%0,%1,%2,%3}, [%4];"
        : "=r"(r[0]), "=r"(r[1]), "=r"(r[2]), "=r"(r[3]) : "r"(addr));
}

__device__ __forceinline__ void mma16816(float* d, const uint32_t* a, const uint32_t* b) {
    asm volatile(
        "mma.sync.aligned.m16n8k16.row.col.f32.bf16.bf16.f32 "
        "{%0,%1,%2,%3}, {%4,%5,%6,%7}, {%8,%9}, {%0,%1,%2,%3};"
        : "+f"(d[0]), "+f"(d[1]), "+f"(d[2]), "+f"(d[3])
        : "r"(a[0]), "r"(a[1]), "r"(a[2]), "r"(a[3]), "r"(b[0]), "r"(b[1]));
}

// ============================================================================
// Kernel 1: row L2-normalize fp32 -> bf16 scratch (chunk-major, pre-swizzled)
// Warp-per-row, barrier-free, COALESCED:
//   loads: lane l reads float4 index l + 32k (adjacent lanes -> adjacent 16B)
//   stores: per k one uint2 (4 bf16); element base e = 4l + 128k ->
//           chunk = 2k + (l>>4), in-row byte off = 8*(l&15)  (half-warp
//           contiguous 128B segments; swizzle preserves 8B alignment)
// 2048 blocks x 128 threads = 8192 warps = 8192 rows (2 matrices x 4096).
// ============================================================================
__global__ void __launch_bounds__(128) norm_bf16_kernel(
    const float* __restrict__ emb_i, const float* __restrict__ emb_j) {
    int wid = threadIdx.x >> 5, lane = threadIdx.x & 31;
    int mat = blockIdx.x >> 10;                      // 0: emb_i, 1: emb_j
    int row = ((blockIdx.x & 1023) << 2) + wid;

    const float4* src = reinterpret_cast<const float4*>(mat ? emb_j : emb_i)
                        + (size_t)row * (D_DIM / 4);
    char* dstBase = reinterpret_cast<char*>(mat ? g_zj : g_zi);

    float4 v[8];
#pragma unroll
    for (int k = 0; k < 8; k++) v[k] = src[lane + 32 * k];   // coalesced
    float ss = 0.0f;
#pragma unroll
    for (int k = 0; k < 8; k++)
        ss += v[k].x * v[k].x + v[k].y * v[k].y + v[k].z * v[k].z + v[k].w * v[k].w;
#pragma unroll
    for (int o = 16; o > 0; o >>= 1) ss += __shfl_xor_sync(0xFFFFFFFFu, ss, o);
    float inv = 1.0f / fmaxf(sqrtf(ss), 1e-12f);

    uint32_t rowOff = (uint32_t)row * 128u + (uint32_t)(lane & 15) * 8u;
    uint32_t swOff = SWZ128(rowOff);
    int chunkBase = lane >> 4;                       // 0 or 1
#pragma unroll
    for (int k = 0; k < 8; k++) {
        __nv_bfloat162 lo = __floats2bfloat162_rn(v[k].x * inv, v[k].y * inv);
        __nv_bfloat162 hi = __floats2bfloat162_rn(v[k].z * inv, v[k].w * inv);
        uint2 pack;
        pack.x = *reinterpret_cast<uint32_t*>(&lo);
        pack.y = *reinterpret_cast<uint32_t*>(&hi);
        int chunk = 2 * k + chunkBase;               // 64-elem K-chunk
        *reinterpret_cast<uint2*>(
            dstBase + (size_t)chunk * CHUNK_MAT_BYTES + swOff) = pack;
    }
}

// ============================================================================
// Kernel 2: fused bf16 mma.sync GEMM + softplus + reduce  (UNCHANGED from R12)
// grid (32, 32): blockIdx.x = tn (TN=128), blockIdx.y = tm (TM=128)
// 256 threads = 8 warps (4 in M x 2 in N), warp tile 32x64.
// 3-stage cp.async pipeline, one __syncthreads per chunk; unconditional
// commit_group keeps wait_group counts exact through the tail.
// 2 CTAs/SM: co-resident CTA's mainloop hides this CTA's prologue/epilogue.
// ============================================================================
__device__ __forceinline__ void issue_loads(uint32_t dA, uint32_t dB,
                                            const char* srcA, const char* srcB,
                                            int tid) {
    // A tile 16384B = 1024 x 16B slices -> 4 per thread
#pragma unroll
    for (int i = 0; i < 4; i++) {
        uint32_t idx = (uint32_t)tid + 256u * i;
        cp_async16(dA + idx * 16u, srcA + (size_t)idx * 16u);
    }
    // B tile 16384B = 1024 x 16B slices -> 4 per thread
#pragma unroll
    for (int i = 0; i < 4; i++) {
        uint32_t idx = (uint32_t)tid + 256u * i;
        cp_async16(dB + idx * 16u, srcB + (size_t)idx * 16u);
    }
}

__global__ void __launch_bounds__(256, 2) gemm_loss_kernel() {
    extern __shared__ __align__(1024) char smem[];
    uint32_t sb = smem_to_u32(smem);
    int tid = threadIdx.x;
    int wid = tid >> 5, lane = tid & 31;
    int wm = wid >> 1, wn = wid & 1;        // 4 x 2 warp grid
    int tn = blockIdx.x, tm = blockIdx.y;

    uint32_t stA[NSTAGE], stB[NSTAGE];
#pragma unroll
    for (int s = 0; s < NSTAGE; s++) {
        stA[s] = sb + 1024 + s * STAGE_BYTES;
        stB[s] = stA[s] + A_TILE_BYTES;
    }

    const char* gA = reinterpret_cast<const char*>(g_zj) + (size_t)tm * TM * 128;
    const char* gB = reinterpret_cast<const char*>(g_zi) + (size_t)tn * TN * 128;

    // Prologue: chunks 0..NSTAGE-2 into stages 0..NSTAGE-2 (one group each)
#pragma unroll
    for (int c = 0; c < NSTAGE - 1; c++) {
        issue_loads(stA[c], stB[c], gA + (size_t)c * CHUNK_MAT_BYTES,
                    gB + (size_t)c * CHUNK_MAT_BYTES, tid);
        CP_COMMIT();
    }

    // Unswizzled ldmatrix byte offsets; swizzle applied per access so the
    // +kk*32 column advance happens BEFORE the XOR — no carry corruption.
    uint32_t aRow[2];
    {
        int r = lane & 15, hb = (lane >> 4) * 16;
#pragma unroll
        for (int i = 0; i < 2; i++)
            aRow[i] = (uint32_t)(wm * 32 + i * 16 + r) * 128u + hb;
    }
    uint32_t bRow[4];
    {
        int rn = (lane & 7) + ((lane >> 4) << 3);
        int bb = ((lane >> 3) & 1) * 16;
#pragma unroll
        for (int j2 = 0; j2 < 4; j2++)
            bRow[j2] = (uint32_t)(wn * 64 + j2 * 16 + rn) * 128u + bb;
    }

    float acc[64];
#pragma unroll
    for (int i = 0; i < 64; i++) acc[i] = 0.0f;

    int sIdx = 0;   // stage of chunk c (cycles 0,1,2,0,...)
    for (int c = 0; c < NCHUNK; c++) {
        CP_WAIT(NSTAGE - 2);   // chunk c's group retired (groups are exact)
        __syncthreads();       // chunk c visible; stage of chunk c-1 free

        int cn = c + NSTAGE - 1;
        int sNext = sIdx + (NSTAGE - 1);
        if (sNext >= NSTAGE) sNext -= NSTAGE;
        if (cn < NCHUNK)
            issue_loads(stA[sNext], stB[sNext],
                        gA + (size_t)cn * CHUNK_MAT_BYTES,
                        gB + (size_t)cn * CHUNK_MAT_BYTES, tid);
        CP_COMMIT();           // unconditional: tail groups may be empty

        uint32_t baseA = stA[sIdx], baseB = stB[sIdx];
#pragma unroll
        for (int kk = 0; kk < 4; kk++) {
            uint32_t af[2][4], bf[4][4];
            ldsm_x4(af[0], baseA + SWZ128(aRow[0] + kk * 32u));
            ldsm_x4(af[1], baseA + SWZ128(aRow[1] + kk * 32u));
#pragma unroll
            for (int j2 = 0; j2 < 4; j2++)
                ldsm_x4(bf[j2], baseB + SWZ128(bRow[j2] + kk * 32u));
#pragma unroll
            for (int i = 0; i < 2; i++)
#pragma unroll
                for (int j = 0; j < 8; j++)
                    mma16816(&acc[(i * 8 + j) * 4], af[i], &bf[j >> 1][(j & 1) * 2]);
        }
        sIdx = (sIdx == NSTAGE - 1) ? 0 : sIdx + 1;
    }

    // ---- fused epilogue: softplus + diagonal split, all in registers ----
    int g = lane >> 2, tig = lane & 3;
    int rowBase = tm * TM + wm * 32;
    int colBase = tn * TN + wn * 64;
    float negs = 0.0f, poss = 0.0f;
#pragma unroll
    for (int i = 0; i < 2; i++) {
#pragma unroll
        for (int j = 0; j < 8; j++) {
            const float* d = &acc[(i * 8 + j) * 4];
#pragma unroll
            for (int r = 0; r < 4; r++) {
                int row = rowBase + i * 16 + g + (r >> 1) * 8;
                int col = colBase + j * 8 + tig * 2 + (r & 1);
                float v = d[r];
                if (row == col) poss += __logf(1.0f + __expf(TEMP - v));
                else            negs += __logf(1.0f + __expf(v - TEMP));
            }
        }
    }
#pragma unroll
    for (int o = 16; o > 0; o >>= 1) {
        negs += __shfl_xor_sync(0xFFFFFFFFu, negs, o);
        poss += __shfl_xor_sync(0xFFFFFFFFu, poss, o);
    }
    float* red = reinterpret_cast<float*>(smem + 32);
    if (lane == 0) { red[wid] = negs; red[8 + wid] = poss; }
    __syncthreads();
    if (tid == 0) {
        float n = 0.0f, p = 0.0f;
#pragma unroll
        for (int w = 0; w < 8; w++) { n += red[w]; p += red[8 + w]; }
        int cta = tm * 32 + tn;
        g_partials[cta * 2]     = n;
        g_partials[cta * 2 + 1] = p;
    }
}

// ============================================================================
// Kernel 3: deterministic final reduction of 1024 CTA partials -> scalar loss
// ============================================================================
__global__ void __launch_bounds__(1024) finalize_kernel(float* __restrict__ out) {
    __shared__ double s[1024];
    int t = threadIdx.x;
    double n = (double)g_partials[t * 2];
    double p = (double)g_partials[t * 2 + 1];
    s[t] = n;
    __syncthreads();
    for (int o = 512; o > 0; o >>= 1) {
        if (t < o) s[t] += s[t + o];
        __syncthreads();
    }
    double ntot = s[0];
    __syncthreads();
    s[t] = p;
    __syncthreads();
    for (int o = 512; o > 0; o >>= 1) {
        if (t < o) s[t] += s[t + o];
        __syncthreads();
    }
    double ptot = s[0];
    if (t == 0) {
        const double Bd = (double)B_ROWS;
        double loss = 0.5 * (ptot / Bd) + 0.5 * (ntot / (Bd * (Bd - 1.0)));
        out[0] = (float)loss;
    }
}

// ============================================================================
// Launcher
// ============================================================================
extern "C" void kernel_launch(void* const* d_in, const int* in_sizes, int n_in,
                              void* d_out, int out_size) {
    (void)in_sizes; (void)n_in; (void)out_size;
    const float* emb_i = (const float*)d_in[0];
    const float* emb_j = (const float*)d_in[1];
    float* out = (float*)d_out;

    cudaFuncSetAttribute(gemm_loss_kernel,
                         cudaFuncAttributeMaxDynamicSharedMemorySize, SMEM_TOTAL);

    norm_bf16_kernel<<<2048, 128>>>(emb_i, emb_j);
    dim3 grid(B_ROWS / TN, B_ROWS / TM);   // (32, 32)
    gemm_loss_kernel<<<grid, 256, SMEM_TOTAL>>>();
    finalize_kernel<<<1, 1024>>>(out);
}

// round 14
// speedup vs baseline: 1.2884x; 1.0249x over previous
#include <cuda_runtime.h>
#include <cuda_bf16.h>
#include <cstdint>

// ============================================================================
// Problem constants
// ============================================================================
#define B_ROWS 4096
#define D_DIM  1024
#define TEMP   0.2f

// GEMM tiling: sim[4096,4096] = z_j (M side) @ z_i^T (N side), bf16 operands
#define TM 128
#define TN 128
#define KC 64                            // bf16 per K-chunk = 128 bytes/row
#define NCHUNK (D_DIM / KC)              // 16
#define CHUNK_MAT_BYTES (B_ROWS * 128)   // 524288 bytes per chunk-slab per matrix

#define A_TILE_BYTES (TM * 128)          // 16384
#define B_TILE_BYTES (TN * 128)          // 16384
#define STAGE_BYTES  (A_TILE_BYTES + B_TILE_BYTES)   // 32768
#define NSTAGE 3

// SMEM: [0..1024) control/reduction, then 3 stages of (A tile | B tile)
#define SMEM_TOTAL (1024 + NSTAGE * STAGE_BYTES)     // 99328  -> 2 CTAs/SM

#define N_CTAS ((B_ROWS / TM) * (B_ROWS / TN))       // 32 * 32 = 1024

// ============================================================================
// Device scratch (static __device__ globals — no allocation allowed)
// bf16, chunk-major, pre-swizzled (SW128): within each 512KB chunk slab,
//   byte offset = SWZ128(row*128 + kbyte). cp.async copies verbatim; smem
//   lands ldmatrix-ready with zero bank conflicts.
// ============================================================================
__device__ __align__(1024) __nv_bfloat16 g_zj[(size_t)B_ROWS * D_DIM];  // M side
__device__ __align__(1024) __nv_bfloat16 g_zi[(size_t)B_ROWS * D_DIM];  // N side
__device__ float g_partials[2 * N_CTAS];
__device__ unsigned g_done = 0;          // last-CTA ticket; reset by last CTA

// ============================================================================
// PTX helpers — base-target only (sm_80-class): cp.async, ldmatrix, mma.sync
// ============================================================================
__device__ __forceinline__ uint32_t smem_to_u32(const void* smem_ptr) {
    uint32_t addr;
    asm("{ .reg .u64 tmp; cvta.to.shared.u64 tmp, %1; cvt.u32.u64 %0, tmp; }"
        : "=r"(addr) : "l"(smem_ptr));
    return addr;
}

#define SWZ128(o) ((o) ^ (((o) >> 3) & 0x70))

__device__ __forceinline__ void cp_async16(uint32_t dst, const void* src) {
    asm volatile("cp.async.cg.shared.global [%0], [%1], 16;"
        :: "r"(dst), "l"(src) : "memory");
}
#define CP_COMMIT() asm volatile("cp.async.commit_group;" ::: "memory")
#define CP_WAIT(n)  asm volatile("cp.async.wait_group %0;" :: "n"(n) : "memory")

__device__ __forceinline__ void ldsm_x4(uint32_t* r, uint32_t addr) {
    asm volatile("ldmatrix.sync.aligned.m8n8.x4.shared.b16 {%0,%1,%2,%3}, [%4];"
        : "=r"(r[0]), "=r"(r[1]), "=r"(r[2]), "=r"(r[3]) : "r"(addr));
}

__device__ __forceinline__ void mma16816(float* d, const uint32_t* a, const uint32_t* b) {
    asm volatile(
        "mma.sync.aligned.m16n8k16.row.col.f32.bf16.bf16.f32 "
        "{%0,%1,%2,%3}, {%4,%5,%6,%7}, {%8,%9}, {%0,%1,%2,%3};"
        : "+f"(d[0]), "+f"(d[1]), "+f"(d[2]), "+f"(d[3])
        : "r"(a[0]), "r"(a[1]), "r"(a[2]), "r"(a[3]), "r"(b[0]), "r"(b[1]));
}

// ============================================================================
// Kernel 1: row L2-normalize fp32 -> bf16 scratch (chunk-major, pre-swizzled)
// Warp-per-row, barrier-free, coalesced, TWO-PASS (low register footprint):
//   pass 1: read row (coalesced float4), accumulate sum-of-squares, discard
//   pass 2: re-read (L1/L2 hit — row is ~4KB/warp, stays cached), scale,
//           pack bf16, swizzled store (half-warp-contiguous 128B segments)
// 2048 blocks x 128 threads = 8192 warps = 8192 rows (2 matrices x 4096).
// ============================================================================
__global__ void __launch_bounds__(128) norm_bf16_kernel(
    const float* __restrict__ emb_i, const float* __restrict__ emb_j) {
    int wid = threadIdx.x >> 5, lane = threadIdx.x & 31;
    int mat = blockIdx.x >> 10;                      // 0: emb_i, 1: emb_j
    int row = ((blockIdx.x & 1023) << 2) + wid;

    const float4* src = reinterpret_cast<const float4*>(mat ? emb_j : emb_i)
                        + (size_t)row * (D_DIM / 4);
    char* dstBase = reinterpret_cast<char*>(mat ? g_zj : g_zi);

    // Pass 1: sum of squares only (no payload kept live)
    float ss = 0.0f;
#pragma unroll
    for (int k = 0; k < 8; k++) {
        float4 t = src[lane + 32 * k];               // coalesced
        ss += t.x * t.x + t.y * t.y + t.z * t.z + t.w * t.w;
    }
#pragma unroll
    for (int o = 16; o > 0; o >>= 1) ss += __shfl_xor_sync(0xFFFFFFFFu, ss, o);
    float inv = 1.0f / fmaxf(sqrtf(ss), 1e-12f);

    // Pass 2: re-read (cache hit), scale, store
    uint32_t rowOff = (uint32_t)row * 128u + (uint32_t)(lane & 15) * 8u;
    uint32_t swOff = SWZ128(rowOff);
    int chunkBase = lane >> 4;                       // 0 or 1
#pragma unroll
    for (int k = 0; k < 8; k++) {
        float4 t = src[lane + 32 * k];
        __nv_bfloat162 lo = __floats2bfloat162_rn(t.x * inv, t.y * inv);
        __nv_bfloat162 hi = __floats2bfloat162_rn(t.z * inv, t.w * inv);
        uint2 pack;
        pack.x = *reinterpret_cast<uint32_t*>(&lo);
        pack.y = *reinterpret_cast<uint32_t*>(&hi);
        int chunk = 2 * k + chunkBase;               // 64-elem K-chunk
        *reinterpret_cast<uint2*>(
            dstBase + (size_t)chunk * CHUNK_MAT_BYTES + swOff) = pack;
    }
}

// ============================================================================
// Kernel 2: fused bf16 mma.sync GEMM + softplus + reduce + LAST-CTA FINALIZE
// grid (32, 32): blockIdx.x = tn (TN=128), blockIdx.y = tm (TM=128)
// 256 threads = 8 warps (4 in M x 2 in N), warp tile 32x64.
// 3-stage cp.async pipeline, one __syncthreads per chunk; unconditional
// commit_group keeps wait_group counts exact through the tail.
// 2 CTAs/SM: co-resident CTA's mainloop hides this CTA's prologue/epilogue.
// Final scalar reduction is done by the LAST CTA to finish (atomic ticket,
// deterministic fixed-order double tree), which also resets the ticket so
// kernel_launch stays graph-replayable.
// ============================================================================
__device__ __forceinline__ void issue_loads(uint32_t dA, uint32_t dB,
                                            const char* srcA, const char* srcB,
                                            int tid) {
    // A tile 16384B = 1024 x 16B slices -> 4 per thread
#pragma unroll
    for (int i = 0; i < 4; i++) {
        uint32_t idx = (uint32_t)tid + 256u * i;
        cp_async16(dA + idx * 16u, srcA + (size_t)idx * 16u);
    }
    // B tile 16384B = 1024 x 16B slices -> 4 per thread
#pragma unroll
    for (int i = 0; i < 4; i++) {
        uint32_t idx = (uint32_t)tid + 256u * i;
        cp_async16(dB + idx * 16u, srcB + (size_t)idx * 16u);
    }
}

__global__ void __launch_bounds__(256, 2) gemm_loss_kernel(float* __restrict__ out) {
    extern __shared__ __align__(1024) char smem[];
    uint32_t sb = smem_to_u32(smem);
    int tid = threadIdx.x;
    int wid = tid >> 5, lane = tid & 31;
    int wm = wid >> 1, wn = wid & 1;        // 4 x 2 warp grid
    int tn = blockIdx.x, tm = blockIdx.y;

    uint32_t stA[NSTAGE], stB[NSTAGE];
#pragma unroll
    for (int s = 0; s < NSTAGE; s++) {
        stA[s] = sb + 1024 + s * STAGE_BYTES;
        stB[s] = stA[s] + A_TILE_BYTES;
    }

    const char* gA = reinterpret_cast<const char*>(g_zj) + (size_t)tm * TM * 128;
    const char* gB = reinterpret_cast<const char*>(g_zi) + (size_t)tn * TN * 128;

    // Prologue: chunks 0..NSTAGE-2 into stages 0..NSTAGE-2 (one group each)
#pragma unroll
    for (int c = 0; c < NSTAGE - 1; c++) {
        issue_loads(stA[c], stB[c], gA + (size_t)c * CHUNK_MAT_BYTES,
                    gB + (size_t)c * CHUNK_MAT_BYTES, tid);
        CP_COMMIT();
    }

    // Unswizzled ldmatrix byte offsets; swizzle applied per access so the
    // +kk*32 column advance happens BEFORE the XOR — no carry corruption.
    uint32_t aRow[2];
    {
        int r = lane & 15, hb = (lane >> 4) * 16;
#pragma unroll
        for (int i = 0; i < 2; i++)
            aRow[i] = (uint32_t)(wm * 32 + i * 16 + r) * 128u + hb;
    }
    uint32_t bRow[4];
    {
        int rn = (lane & 7) + ((lane >> 4) << 3);
        int bb = ((lane >> 3) & 1) * 16;
#pragma unroll
        for (int j2 = 0; j2 < 4; j2++)
            bRow[j2] = (uint32_t)(wn * 64 + j2 * 16 + rn) * 128u + bb;
    }

    float acc[64];
#pragma unroll
    for (int i = 0; i < 64; i++) acc[i] = 0.0f;

    int sIdx = 0;   // stage of chunk c (cycles 0,1,2,0,...)
    for (int c = 0; c < NCHUNK; c++) {
        CP_WAIT(NSTAGE - 2);   // chunk c's group retired (groups are exact)
        __syncthreads();       // chunk c visible; stage of chunk c-1 free

        int cn = c + NSTAGE - 1;
        int sNext = sIdx + (NSTAGE - 1);
        if (sNext >= NSTAGE) sNext -= NSTAGE;
        if (cn < NCHUNK)
            issue_loads(stA[sNext], stB[sNext],
                        gA + (size_t)cn * CHUNK_MAT_BYTES,
                        gB + (size_t)cn * CHUNK_MAT_BYTES, tid);
        CP_COMMIT();           // unconditional: tail groups may be empty

        uint32_t baseA = stA[sIdx], baseB = stB[sIdx];
#pragma unroll
        for (int kk = 0; kk < 4; kk++) {
            uint32_t af[2][4], bf[4][4];
            ldsm_x4(af[0], baseA + SWZ128(aRow[0] + kk * 32u));
            ldsm_x4(af[1], baseA + SWZ128(aRow[1] + kk * 32u));
#pragma unroll
            for (int j2 = 0; j2 < 4; j2++)
                ldsm_x4(bf[j2], baseB + SWZ128(bRow[j2] + kk * 32u));
#pragma unroll
            for (int i = 0; i < 2; i++)
#pragma unroll
                for (int j = 0; j < 8; j++)
                    mma16816(&acc[(i * 8 + j) * 4], af[i], &bf[j >> 1][(j & 1) * 2]);
        }
        sIdx = (sIdx == NSTAGE - 1) ? 0 : sIdx + 1;
    }

    // ---- fused epilogue: softplus + diagonal split, all in registers ----
    int g = lane >> 2, tig = lane & 3;
    int rowBase = tm * TM + wm * 32;
    int colBase = tn * TN + wn * 64;
    float negs = 0.0f, poss = 0.0f;
#pragma unroll
    for (int i = 0; i < 2; i++) {
#pragma unroll
        for (int j = 0; j < 8; j++) {
            const float* d = &acc[(i * 8 + j) * 4];
#pragma unroll
            for (int r = 0; r < 4; r++) {
                int row = rowBase + i * 16 + g + (r >> 1) * 8;
                int col = colBase + j * 8 + tig * 2 + (r & 1);
                float v = d[r];
                if (row == col) poss += __logf(1.0f + __expf(TEMP - v));
                else            negs += __logf(1.0f + __expf(v - TEMP));
            }
        }
    }
#pragma unroll
    for (int o = 16; o > 0; o >>= 1) {
        negs += __shfl_xor_sync(0xFFFFFFFFu, negs, o);
        poss += __shfl_xor_sync(0xFFFFFFFFu, poss, o);
    }
    float* red = reinterpret_cast<float*>(smem + 32);
    if (lane == 0) { red[wid] = negs; red[8 + wid] = poss; }
    __syncthreads();
    if (tid == 0) {
        float n = 0.0f, p = 0.0f;
#pragma unroll
        for (int w = 0; w < 8; w++) { n += red[w]; p += red[8 + w]; }
        int cta = tm * 32 + tn;
        g_partials[cta * 2]     = n;
        g_partials[cta * 2 + 1] = p;
    }

    // ---- last-CTA finalize (deterministic fixed-order double reduction) ----
    __shared__ unsigned isLast;
    __threadfence();                       // publish g_partials before ticket
    if (tid == 0) {
        unsigned v = atomicAdd(&g_done, 1u);
        isLast = (v == (unsigned)(N_CTAS - 1)) ? 1u : 0u;
    }
    __syncthreads();
    if (isLast) {
        __threadfence();                   // acquire: all partials visible
        double* sd = reinterpret_cast<double*>(smem + 1024);  // stage area free
        double n = 0.0, p = 0.0;
#pragma unroll
        for (int i = 0; i < N_CTAS / 256; i++) {   // fixed order: 4 per thread
            int idx = tid + 256 * i;
            n += (double)g_partials[idx * 2];
            p += (double)g_partials[idx * 2 + 1];
        }
        sd[tid] = n;
        sd[256 + tid] = p;
        __syncthreads();
        for (int o = 128; o > 0; o >>= 1) {
            if (tid < o) {
                sd[tid] += sd[tid + o];
                sd[256 + tid] += sd[256 + tid + o];
            }
            __syncthreads();
        }
        if (tid == 0) {
            const double Bd = (double)B_ROWS;
            double loss = 0.5 * (sd[256] / Bd) + 0.5 * (sd[0] / (Bd * (Bd - 1.0)));
            out[0] = (float)loss;
            g_done = 0;                    // reset for next graph replay
        }
    }
}

// ============================================================================
// Launcher
// ============================================================================
extern "C" void kernel_launch(void* const* d_in, const int* in_sizes, int n_in,
                              void* d_out, int out_size) {
    (void)in_sizes; (void)n_in; (void)out_size;
    const float* emb_i = (const float*)d_in[0];
    const float* emb_j = (const float*)d_in[1];
    float* out = (float*)d_out;

    cudaFuncSetAttribute(gemm_loss_kernel,
                         cudaFuncAttributeMaxDynamicSharedMemorySize, SMEM_TOTAL);

    norm_bf16_kernel<<<2048, 128>>>(emb_i, emb_j);
    dim3 grid(B_ROWS / TN, B_ROWS / TM);   // (32, 32)
    gemm_loss_kernel<<<grid, 256, SMEM_TOTAL>>>(out);
}

// round 15
// speedup vs baseline: 1.3182x; 1.0232x over previous
#include <cuda_runtime.h>
#include <cuda_bf16.h>
#include <cstdint>

// ============================================================================
// Problem constants
// ============================================================================
#define B_ROWS 4096
#define D_DIM  1024
#define TEMP   0.2f

// GEMM tiling: sim[4096,4096] = z_j (M side) @ z_i^T (N side), bf16 operands
#define TM 128
#define TN 128
#define KC 64                            // bf16 per K-chunk = 128 bytes/row
#define NCHUNK (D_DIM / KC)              // 16
#define CHUNK_MAT_BYTES (B_ROWS * 128)   // 524288 bytes per chunk-slab per matrix

#define A_TILE_BYTES (TM * 128)          // 16384
#define B_TILE_BYTES (TN * 128)          // 16384
#define STAGE_BYTES  (A_TILE_BYTES + B_TILE_BYTES)   // 32768
#define NSTAGE 3

// SMEM: [0..1024) control/reduction, then 3 stages of (A tile | B tile)
#define SMEM_TOTAL (1024 + NSTAGE * STAGE_BYTES)     // 99328  -> 2 CTAs/SM

#define N_CTAS ((B_ROWS / TM) * (B_ROWS / TN))       // 32 * 32 = 1024
#define CTA_THREADS 128                              // 4 warps, 2x2, tile 64x64

// ============================================================================
// Device scratch (static __device__ globals — no allocation allowed)
// bf16, chunk-major, pre-swizzled (SW128): within each 512KB chunk slab,
//   byte offset = SWZ128(row*128 + kbyte). cp.async copies verbatim; smem
//   lands ldmatrix-ready with zero bank conflicts.
// ============================================================================
__device__ __align__(1024) __nv_bfloat16 g_zj[(size_t)B_ROWS * D_DIM];  // M side
__device__ __align__(1024) __nv_bfloat16 g_zi[(size_t)B_ROWS * D_DIM];  // N side
__device__ float g_partials[2 * N_CTAS];
__device__ unsigned g_done = 0;          // last-CTA ticket; reset by last CTA

// ============================================================================
// PTX helpers — base-target only (sm_80-class): cp.async, ldmatrix, mma.sync
// ============================================================================
__device__ __forceinline__ uint32_t smem_to_u32(const void* smem_ptr) {
    uint32_t addr;
    asm("{ .reg .u64 tmp; cvta.to.shared.u64 tmp, %1; cvt.u32.u64 %0, tmp; }"
        : "=r"(addr) : "l"(smem_ptr));
    return addr;
}

#define SWZ128(o) ((o) ^ (((o) >> 3) & 0x70))

__device__ __forceinline__ void cp_async16(uint32_t dst, const void* src) {
    asm volatile("cp.async.cg.shared.global [%0], [%1], 16;"
        :: "r"(dst), "l"(src) : "memory");
}
#define CP_COMMIT() asm volatile("cp.async.commit_group;" ::: "memory")
#define CP_WAIT(n)  asm volatile("cp.async.wait_group %0;" :: "n"(n) : "memory")

__device__ __forceinline__ void ldsm_x4(uint32_t* r, uint32_t addr) {
    asm volatile("ldmatrix.sync.aligned.m8n8.x4.shared.b16 {%0,%1,%2,%3}, [%4];"
        : "=r"(r[0]), "=r"(r[1]), "=r"(r[2]), "=r"(r[3]) : "r"(addr));
}

__device__ __forceinline__ void mma16816(float* d, const uint32_t* a, const uint32_t* b) {
    asm volatile(
        "mma.sync.aligned.m16n8k16.row.col.f32.bf16.bf16.f32 "
        "{%0,%1,%2,%3}, {%4,%5,%6,%7}, {%8,%9}, {%0,%1,%2,%3};"
        : "+f"(d[0]), "+f"(d[1]), "+f"(d[2]), "+f"(d[3])
        : "r"(a[0]), "r"(a[1]), "r"(a[2]), "r"(a[3]), "r"(b[0]), "r"(b[1]));
}

// ============================================================================
// Kernel 1: row L2-normalize fp32 -> bf16 scratch (chunk-major, pre-swizzled)
// Warp-per-row, barrier-free, coalesced, two-pass (UNCHANGED from R14).
// 2048 blocks x 128 threads = 8192 warps = 8192 rows (2 matrices x 4096).
// ============================================================================
__global__ void __launch_bounds__(128) norm_bf16_kernel(
    const float* __restrict__ emb_i, const float* __restrict__ emb_j) {
    int wid = threadIdx.x >> 5, lane = threadIdx.x & 31;
    int mat = blockIdx.x >> 10;                      // 0: emb_i, 1: emb_j
    int row = ((blockIdx.x & 1023) << 2) + wid;

    const float4* src = reinterpret_cast<const float4*>(mat ? emb_j : emb_i)
                        + (size_t)row * (D_DIM / 4);
    char* dstBase = reinterpret_cast<char*>(mat ? g_zj : g_zi);

    // Pass 1: sum of squares only (no payload kept live)
    float ss = 0.0f;
#pragma unroll
    for (int k = 0; k < 8; k++) {
        float4 t = src[lane + 32 * k];               // coalesced
        ss += t.x * t.x + t.y * t.y + t.z * t.z + t.w * t.w;
    }
#pragma unroll
    for (int o = 16; o > 0; o >>= 1) ss += __shfl_xor_sync(0xFFFFFFFFu, ss, o);
    float inv = 1.0f / fmaxf(sqrtf(ss), 1e-12f);

    // Pass 2: re-read (cache hit), scale, store
    uint32_t rowOff = (uint32_t)row * 128u + (uint32_t)(lane & 15) * 8u;
    uint32_t swOff = SWZ128(rowOff);
    int chunkBase = lane >> 4;                       // 0 or 1
#pragma unroll
    for (int k = 0; k < 8; k++) {
        float4 t = src[lane + 32 * k];
        __nv_bfloat162 lo = __floats2bfloat162_rn(t.x * inv, t.y * inv);
        __nv_bfloat162 hi = __floats2bfloat162_rn(t.z * inv, t.w * inv);
        uint2 pack;
        pack.x = *reinterpret_cast<uint32_t*>(&lo);
        pack.y = *reinterpret_cast<uint32_t*>(&hi);
        int chunk = 2 * k + chunkBase;               // 64-elem K-chunk
        *reinterpret_cast<uint2*>(
            dstBase + (size_t)chunk * CHUNK_MAT_BYTES + swOff) = pack;
    }
}

// ============================================================================
// Kernel 2: fused bf16 mma.sync GEMM + softplus + reduce + last-CTA finalize
// grid (32, 32); 128 threads = 4 warps in 2x2, warp tile 64x64 (acc 128 regs).
// Raises MMA:ldsm ratio 2x vs 32x64 tiles: smem reads drop 96KB->64KB per
// CTA-chunk, decongesting the L1 crossbar that capped tensor at 60%.
// 3-stage cp.async pipeline, one __syncthreads per chunk; unconditional
// commit_group keeps wait_group counts exact through the tail. 2 CTAs/SM.
// ============================================================================
__device__ __forceinline__ void issue_loads(uint32_t dA, uint32_t dB,
                                            const char* srcA, const char* srcB,
                                            int tid) {
    // A tile 16384B = 1024 x 16B slices -> 8 per thread (128 threads)
#pragma unroll
    for (int i = 0; i < 8; i++) {
        uint32_t idx = (uint32_t)tid + 128u * i;
        cp_async16(dA + idx * 16u, srcA + (size_t)idx * 16u);
    }
    // B tile 16384B = 1024 x 16B slices -> 8 per thread
#pragma unroll
    for (int i = 0; i < 8; i++) {
        uint32_t idx = (uint32_t)tid + 128u * i;
        cp_async16(dB + idx * 16u, srcB + (size_t)idx * 16u);
    }
}

__global__ void __launch_bounds__(CTA_THREADS, 2) gemm_loss_kernel(float* __restrict__ out) {
    extern __shared__ __align__(1024) char smem[];
    uint32_t sb = smem_to_u32(smem);
    int tid = threadIdx.x;
    int wid = tid >> 5, lane = tid & 31;
    int wm = wid >> 1, wn = wid & 1;        // 2 x 2 warp grid, warp tile 64x64
    int tn = blockIdx.x, tm = blockIdx.y;

    uint32_t stA[NSTAGE], stB[NSTAGE];
#pragma unroll
    for (int s = 0; s < NSTAGE; s++) {
        stA[s] = sb + 1024 + s * STAGE_BYTES;
        stB[s] = stA[s] + A_TILE_BYTES;
    }

    const char* gA = reinterpret_cast<const char*>(g_zj) + (size_t)tm * TM * 128;
    const char* gB = reinterpret_cast<const char*>(g_zi) + (size_t)tn * TN * 128;

    // Prologue: chunks 0..NSTAGE-2 into stages 0..NSTAGE-2 (one group each)
#pragma unroll
    for (int c = 0; c < NSTAGE - 1; c++) {
        issue_loads(stA[c], stB[c], gA + (size_t)c * CHUNK_MAT_BYTES,
                    gB + (size_t)c * CHUNK_MAT_BYTES, tid);
        CP_COMMIT();
    }

    // Unswizzled ldmatrix byte offsets; swizzle applied per access so the
    // +kk*32 column advance happens BEFORE the XOR — no carry corruption.
    uint32_t aRow[4];
    {
        int r = lane & 15, hb = (lane >> 4) * 16;
#pragma unroll
        for (int i = 0; i < 4; i++)
            aRow[i] = (uint32_t)(wm * 64 + i * 16 + r) * 128u + hb;
    }
    uint32_t bRow[4];
    {
        int rn = (lane & 7) + ((lane >> 4) << 3);
        int bb = ((lane >> 3) & 1) * 16;
#pragma unroll
        for (int j2 = 0; j2 < 4; j2++)
            bRow[j2] = (uint32_t)(wn * 64 + j2 * 16 + rn) * 128u + bb;
    }

    float acc[128];
#pragma unroll
    for (int i = 0; i < 128; i++) acc[i] = 0.0f;

    int sIdx = 0;   // stage of chunk c (cycles 0,1,2,0,...)
    for (int c = 0; c < NCHUNK; c++) {
        CP_WAIT(NSTAGE - 2);   // chunk c's group retired (groups are exact)
        __syncthreads();       // chunk c visible; stage of chunk c-1 free

        int cn = c + NSTAGE - 1;
        int sNext = sIdx + (NSTAGE - 1);
        if (sNext >= NSTAGE) sNext -= NSTAGE;
        if (cn < NCHUNK)
            issue_loads(stA[sNext], stB[sNext],
                        gA + (size_t)cn * CHUNK_MAT_BYTES,
                        gB + (size_t)cn * CHUNK_MAT_BYTES, tid);
        CP_COMMIT();           // unconditional: tail groups may be empty

        uint32_t baseA = stA[sIdx], baseB = stB[sIdx];
#pragma unroll
        for (int kk = 0; kk < 4; kk++) {
            uint32_t af[4][4], bf[4][4];
#pragma unroll
            for (int i = 0; i < 4; i++)
                ldsm_x4(af[i], baseA + SWZ128(aRow[i] + kk * 32u));
#pragma unroll
            for (int j2 = 0; j2 < 4; j2++)
                ldsm_x4(bf[j2], baseB + SWZ128(bRow[j2] + kk * 32u));
#pragma unroll
            for (int i = 0; i < 4; i++)
#pragma unroll
                for (int j = 0; j < 8; j++)
                    mma16816(&acc[(i * 8 + j) * 4], af[i], &bf[j >> 1][(j & 1) * 2]);
        }
        sIdx = (sIdx == NSTAGE - 1) ? 0 : sIdx + 1;
    }

    // ---- fused epilogue: softplus + diagonal split, all in registers ----
    int g = lane >> 2, tig = lane & 3;
    int rowBase = tm * TM + wm * 64;
    int colBase = tn * TN + wn * 64;
    float negs = 0.0f, poss = 0.0f;
#pragma unroll
    for (int i = 0; i < 4; i++) {
#pragma unroll
        for (int j = 0; j < 8; j++) {
            const float* d = &acc[(i * 8 + j) * 4];
#pragma unroll
            for (int r = 0; r < 4; r++) {
                int row = rowBase + i * 16 + g + (r >> 1) * 8;
                int col = colBase + j * 8 + tig * 2 + (r & 1);
                float v = d[r];
                if (row == col) poss += __logf(1.0f + __expf(TEMP - v));
                else            negs += __logf(1.0f + __expf(v - TEMP));
            }
        }
    }
#pragma unroll
    for (int o = 16; o > 0; o >>= 1) {
        negs += __shfl_xor_sync(0xFFFFFFFFu, negs, o);
        poss += __shfl_xor_sync(0xFFFFFFFFu, poss, o);
    }
    float* red = reinterpret_cast<float*>(smem + 32);
    if (lane == 0) { red[wid] = negs; red[4 + wid] = poss; }
    __syncthreads();
    if (tid == 0) {
        float n = red[0] + red[1] + red[2] + red[3];
        float p = red[4] + red[5] + red[6] + red[7];
        int cta = tm * 32 + tn;
        g_partials[cta * 2]     = n;
        g_partials[cta * 2 + 1] = p;
    }

    // ---- last-CTA finalize (deterministic fixed-order double reduction) ----
    __shared__ unsigned isLast;
    __threadfence();                       // publish g_partials before ticket
    if (tid == 0) {
        unsigned v = atomicAdd(&g_done, 1u);
        isLast = (v == (unsigned)(N_CTAS - 1)) ? 1u : 0u;
    }
    __syncthreads();
    if (isLast) {
        __threadfence();                   // acquire: all partials visible
        double* sd = reinterpret_cast<double*>(smem + 1024);  // stage area free
        double n = 0.0, p = 0.0;
#pragma unroll
        for (int i = 0; i < N_CTAS / CTA_THREADS; i++) {   // fixed order: 8/thread
            int idx = tid + CTA_THREADS * i;
            n += (double)g_partials[idx * 2];
            p += (double)g_partials[idx * 2 + 1];
        }
        sd[tid] = n;
        sd[CTA_THREADS + tid] = p;
        __syncthreads();
        for (int o = CTA_THREADS / 2; o > 0; o >>= 1) {
            if (tid < o) {
                sd[tid] += sd[tid + o];
                sd[CTA_THREADS + tid] += sd[CTA_THREADS + tid + o];
            }
            __syncthreads();
        }
        if (tid == 0) {
            const double Bd = (double)B_ROWS;
            double loss = 0.5 * (sd[CTA_THREADS] / Bd)
                        + 0.5 * (sd[0] / (Bd * (Bd - 1.0)));
            out[0] = (float)loss;
            g_done = 0;                    // reset for next graph replay
        }
    }
}

// ============================================================================
// Launcher
// ============================================================================
extern "C" void kernel_launch(void* const* d_in, const int* in_sizes, int n_in,
                              void* d_out, int out_size) {
    (void)in_sizes; (void)n_in; (void)out_size;
    const float* emb_i = (const float*)d_in[0];
    const float* emb_j = (const float*)d_in[1];
    float* out = (float*)d_out;

    cudaFuncSetAttribute(gemm_loss_kernel,
                         cudaFuncAttributeMaxDynamicSharedMemorySize, SMEM_TOTAL);

    norm_bf16_kernel<<<2048, 128>>>(emb_i, emb_j);
    dim3 grid(B_ROWS / TN, B_ROWS / TM);   // (32, 32)
    gemm_loss_kernel<<<grid, CTA_THREADS, SMEM_TOTAL>>>(out);
}